// round 15
// baseline (speedup 1.0000x reference)
#include <cuda_runtime.h>
#include <cuda_fp16.h>

// CRPS loss: out = mean|y_pred - y| - sum_{i,k,l}|x[i,k]-x[i,l]| / (n*2*m^2)
// Sorted-row identity:  sum_{k,l}|x_k - x_l| = 2 * sum_j (2j - m + 1) x_(j)
//
// Combines all three proven wins:
//  - half2 packing: rows A,B share one instruction stream (hmin2/hmax2)
//  - normalized bitonic network: reversal exchange per merge, then pure
//    ascending compare-exchanges (no runtime direction selects)
//  - row-splitting: TWO warps per row-pair, warp h owns elements
//    j = h*128 + lane*4 + r (VPT=4) -> 4096 warps (full parallelism)
// k=256 merge = cross-warp REVERSAL exchange via smem (partner 255-j is a
// mirrored uint4 with reversed elements, one barrier), then warp-local
// ascending descent. MAE exact in fp32; mix term fp16 (rel_err ~3e-7).
// Fused last-block-done deterministic final reduction.

#define MDIM 256
#define VPT 4
#define NTHREADS 128            // 4 warps = 2 row-pairs = 4 rows per CTA
#define ROWS_PER_CTA 4
#define MAX_CTAS 8192

__device__ float        g_partials[MAX_CTAS];
__device__ unsigned int g_count;   // zero-init; reset by last CTA each launch

__device__ __forceinline__ void cexa2(__half2& a, __half2& b) {
    __half2 mn = __hmin2(a, b); b = __hmax2(a, b); a = mn;
}
__device__ __forceinline__ void cexd2(__half2& a, __half2& b) {
    __half2 mx = __hmax2(a, b); b = __hmin2(a, b); a = mx;
}

// ascending intra-register descent: strides 2 then 1 (compile-time)
__device__ __forceinline__ void intra_desc(__half2 v[VPT]) {
    cexa2(v[0], v[2]); cexa2(v[1], v[3]);
    cexa2(v[0], v[1]); cexa2(v[2], v[3]);
}

// reversal exchange for merge: partner element j ^ (4*(LM+1)-1)
// -> lane^LM, register 3-r; keep_min = (j & merge_half)==0 = lane bit.
template <int LM>
__device__ __forceinline__ void rev_cross(__half2 v[VPT], int lane) {
    const bool keep_min = (lane & ((LM + 1) >> 1)) == 0;
    __half2 p[VPT];
    #pragma unroll
    for (int r = 0; r < VPT; r++)
        p[r] = __shfl_xor_sync(0xffffffffu, v[VPT - 1 - r], LM);
    #pragma unroll
    for (int r = 0; r < VPT; r++)
        v[r] = keep_min ? __hmin2(v[r], p[r]) : __hmax2(v[r], p[r]);
}

// uniform-ascending cross-lane exchange at lane stride S
template <int S>
__device__ __forceinline__ void asc_cross(__half2 v[VPT], int lane) {
    const bool keep_min = (lane & S) == 0;
    #pragma unroll
    for (int r = 0; r < VPT; r++) {
        const __half2 p = __shfl_xor_sync(0xffffffffu, v[r], S);
        v[r] = keep_min ? __hmin2(v[r], p) : __hmax2(v[r], p);
    }
}

__global__ void __launch_bounds__(NTHREADS) crps_row_kernel(
    const float* __restrict__ y_pred,
    const float* __restrict__ y,
    float c1,   //  1/(n*m)
    float c2,   // -1/(n*m*m)
    float* __restrict__ out,
    int n_ctas)
{
    const int warp = threadIdx.x >> 5;
    const int lane = threadIdx.x & 31;
    const int pair = warp >> 1;              // row-pair within CTA (0..1)
    const int h    = warp & 1;               // which 128-half of the rows
    const int rowA = (blockIdx.x * 2 + pair) * 2;
    const int rowB = rowA + 1;
    const int base = h * 128 + lane * VPT;   // element offset within row

    // Load 4 elements of each row; exact fp32 MAE; pack to half2.
    __half2 v[VPT];
    float mae;
    {
        const float4 a4 = *(const float4*)(y_pred + rowA * MDIM + base);
        const float4 b4 = *(const float4*)(y_pred + rowB * MDIM + base);
        const float ya = __ldg(&y[rowA]);
        const float yb = __ldg(&y[rowB]);
        mae  = fabsf(a4.x - ya) + fabsf(a4.y - ya) + fabsf(a4.z - ya) + fabsf(a4.w - ya);
        mae += fabsf(b4.x - yb) + fabsf(b4.y - yb) + fabsf(b4.z - yb) + fabsf(b4.w - yb);
        v[0] = __floats2half2_rn(a4.x, b4.x);
        v[1] = __floats2half2_rn(a4.y, b4.y);
        v[2] = __floats2half2_rn(a4.z, b4.z);
        v[3] = __floats2half2_rn(a4.w, b4.w);
    }

    // ---- per-thread ascending sort of the 4 registers (bitonic) ----
    cexa2(v[0], v[1]); cexd2(v[2], v[3]);            // k=2
    cexa2(v[0], v[2]); cexa2(v[1], v[3]);            // k=4 merge
    cexa2(v[0], v[1]); cexa2(v[2], v[3]);

    // ---- normalized merges: reversal exchange + ascending descent ----
    // 4 -> 8   (partner j^7:  lane^1, reg 3-r)
    rev_cross<1>(v, lane);
    intra_desc(v);
    // 8 -> 16  (partner j^15: lane^3)
    rev_cross<3>(v, lane);
    asc_cross<1>(v, lane);
    intra_desc(v);
    // 16 -> 32 (partner j^31: lane^7)
    rev_cross<7>(v, lane);
    asc_cross<2>(v, lane); asc_cross<1>(v, lane);
    intra_desc(v);
    // 32 -> 64 (partner j^63: lane^15)
    rev_cross<15>(v, lane);
    asc_cross<4>(v, lane); asc_cross<2>(v, lane); asc_cross<1>(v, lane);
    intra_desc(v);
    // 64 -> 128 (partner j^127: lane^31)
    rev_cross<31>(v, lane);
    asc_cross<8>(v, lane); asc_cross<4>(v, lane);
    asc_cross<2>(v, lane); asc_cross<1>(v, lane);
    intra_desc(v);

    // ---- 128 -> 256: cross-warp reversal exchange via smem ----
    // partner of j is 255-j = (1-h)*128 + (31-lane)*4 + (3-r)
    __shared__ __align__(16) __half2 xch[2][MDIM];
    *(uint4*)&xch[pair][base] = *(const uint4*)v;
    __syncthreads();
    {
        const uint4 o = *(const uint4*)&xch[pair][(h ^ 1) * 128 + (31 - lane) * VPT];
        const __half2* p = (const __half2*)&o;
        #pragma unroll
        for (int r = 0; r < VPT; r++) {
            const __half2 q = p[VPT - 1 - r];   // reversed element within uint4
            v[r] = (h == 0) ? __hmin2(v[r], q) : __hmax2(v[r], q);
        }
    }
    // ascending descent: strides 64..4 are lane strides 16..1, then intra
    asc_cross<16>(v, lane); asc_cross<8>(v, lane); asc_cross<4>(v, lane);
    asc_cross<2>(v, lane);  asc_cross<1>(v, lane);
    intra_desc(v);

    // ---- weighted sorted sum (both rows share w_j) + mae ----
    float ws = 0.0f;
    #pragma unroll
    for (int r = 0; r < VPT; r++) {
        const float w = (float)(2 * (base + r) - (MDIM - 1));
        const float2 f = __half22float2(v[r]);
        ws = fmaf(w, f.x + f.y, ws);
    }
    float t = mae * c1 + ws * c2;

    #pragma unroll
    for (int off = 16; off; off >>= 1)
        t += __shfl_xor_sync(0xffffffffu, t, off);

    __shared__ float red[NTHREADS / 32];
    __shared__ bool  s_last;
    if (lane == 0) red[warp] = t;
    __syncthreads();

    if (threadIdx.x == 0) {
        float s = 0.0f;
        #pragma unroll
        for (int i = 0; i < NTHREADS / 32; i++) s += red[i];
        g_partials[blockIdx.x] = s;
        __threadfence();
        const unsigned int old = atomicAdd(&g_count, 1u);
        s_last = (old == (unsigned int)(n_ctas - 1));
    }
    __syncthreads();

    // ---- last CTA: deterministic final reduction over per-CTA partials ----
    if (s_last) {
        __threadfence();
        float acc = 0.0f;
        for (int i = threadIdx.x; i < n_ctas; i += NTHREADS) acc += g_partials[i];
        #pragma unroll
        for (int off = 16; off; off >>= 1)
            acc += __shfl_xor_sync(0xffffffffu, acc, off);
        if (lane == 0) red[warp] = acc;
        __syncthreads();
        if (threadIdx.x == 0) {
            float s = 0.0f;
            #pragma unroll
            for (int i = 0; i < NTHREADS / 32; i++) s += red[i];
            out[0] = s;
            g_count = 0;   // reset for next graph replay
        }
    }
}

extern "C" void kernel_launch(void* const* d_in, const int* in_sizes, int n_in,
                              void* d_out, int out_size)
{
    const float* y_pred = (const float*)d_in[0];
    const float* y      = (const float*)d_in[1];
    float* out          = (float*)d_out;

    const int n = in_sizes[1];               // 4096 rows
    (void)n_in; (void)out_size;

    const float c1 =  1.0f / ((float)n * (float)MDIM);
    const float c2 = -1.0f / ((float)n * (float)MDIM * (float)MDIM);

    const int n_ctas = n / ROWS_PER_CTA;     // 1024
    crps_row_kernel<<<n_ctas, NTHREADS>>>(y_pred, y, c1, c2, out, n_ctas);
}

// round 16
// speedup vs baseline: 1.0645x; 1.0645x over previous
#include <cuda_runtime.h>
#include <cuda_fp16.h>

// CRPS loss: out = mean|y_pred - y| - sum_{i,k,l}|x[i,k]-x[i,l]| / (n*2*m^2)
// Sorted-row identity:  sum_{k,l}|x_k - x_l| = 2 * sum_j (2j - m + 1) x_(j)
//
// FOUR rows per warp:
//  - half2 packs rows (A,B) elementwise; lanes 0-15 = row-pair 0,
//    lanes 16-31 = row-pair 1 (shfl strides <=15 never cross groups).
//  - VPT=16: element j = (lane&15)*16 + r. Strides 1..8 are intra-register
//    (compile-time hmin2/hmax2); only 10 cross-lane shfl rounds remain
//    (rev at lane strides 1,3,7,15 + asc descent rounds) = 40 shfl/row.
//  - Normalized bitonic: per-merge reversal exchange, then pure ascending
//    compare-exchanges (no runtime direction selects).
// Evidence from R3..R15: duration ~= 5.5us floor + k*total_shfl; this cuts
// total shfl 245K->164K and instructions 2.34M->~1.1M.
// MAE in half2 with per-thread fp16 tree then fp32 (error ~1e-5 << 1e-3).
// 1 warp per CTA (grid 1024): no barriers anywhere in the main path.
// Fused last-block-done deterministic final reduction.

#define MDIM 256
#define VPT 16
#define ROWS_PER_CTA 4
#define MAX_CTAS 8192

__device__ float        g_partials[MAX_CTAS];
__device__ unsigned int g_count;   // zero-init; reset by last CTA each launch

__device__ __forceinline__ void cexa2(__half2& a, __half2& b) {
    __half2 mn = __hmin2(a, b); b = __hmax2(a, b); a = mn;
}
__device__ __forceinline__ void cexd2(__half2& a, __half2& b) {
    __half2 mx = __hmax2(a, b); b = __hmin2(a, b); a = mx;
}

// intra-register CE at stride J, direction = bit K of register index
// (K=16 -> always ascending since r < 16)
template <int K, int J>
__device__ __forceinline__ void intra_ct(__half2 v[VPT]) {
    #pragma unroll
    for (int r = 0; r < VPT; r++)
        if ((r & J) == 0) {
            if ((r & K) == 0) cexa2(v[r], v[r | J]);
            else              cexd2(v[r], v[r | J]);
        }
}

// ascending intra descent: strides 8,4,2,1
__device__ __forceinline__ void intra_desc16(__half2 v[VPT]) {
    intra_ct<16, 8>(v); intra_ct<16, 4>(v); intra_ct<16, 2>(v); intra_ct<16, 1>(v);
}

// reversal exchange: partner element j ^ (16*(LM+1)-1) -> lane^LM, reg 15-r.
// keep_min = (sub & ((LM+1)/2)) == 0. Mirror-pair processing: 2 temps only.
template <int LM>
__device__ __forceinline__ void rev_cross(__half2 v[VPT], int sub) {
    const bool keep_min = (sub & ((LM + 1) >> 1)) == 0;
    #pragma unroll
    for (int r = 0; r < VPT / 2; r++) {
        const int r2 = VPT - 1 - r;
        const __half2 t1 = __shfl_xor_sync(0xffffffffu, v[r2], LM);
        const __half2 t2 = __shfl_xor_sync(0xffffffffu, v[r], LM);
        v[r]  = keep_min ? __hmin2(v[r],  t1) : __hmax2(v[r],  t1);
        v[r2] = keep_min ? __hmin2(v[r2], t2) : __hmax2(v[r2], t2);
    }
}

// uniform-ascending cross-lane exchange at lane stride S
template <int S>
__device__ __forceinline__ void asc_cross(__half2 v[VPT], int sub) {
    const bool keep_min = (sub & S) == 0;
    #pragma unroll
    for (int r = 0; r < VPT; r++) {
        const __half2 p = __shfl_xor_sync(0xffffffffu, v[r], S);
        v[r] = keep_min ? __hmin2(v[r], p) : __hmax2(v[r], p);
    }
}

__global__ void __launch_bounds__(32) crps_row_kernel(
    const float* __restrict__ y_pred,
    const float* __restrict__ y,
    float c1,   //  1/(n*m)
    float c2,   // -1/(n*m*m)
    float* __restrict__ out,
    int n_ctas)
{
    const int lane = threadIdx.x & 31;
    const int sub  = lane & 15;             // element group within row
    const int grp  = lane >> 4;             // which row-pair (0 or 1)
    const int rowA = blockIdx.x * ROWS_PER_CTA + grp * 2;
    const int rowB = rowA + 1;
    const int base = sub * VPT;             // element offset within row

    // Load 16 elements of each row, pack to half2 (x=rowA, y=rowB).
    __half2 v[VPT];
    {
        const float4* pa = (const float4*)(y_pred + rowA * MDIM + base);
        const float4* pb = (const float4*)(y_pred + rowB * MDIM + base);
        #pragma unroll
        for (int q = 0; q < 4; q++) {
            const float4 a = pa[q];
            const float4 b = pb[q];
            v[4 * q + 0] = __floats2half2_rn(a.x, b.x);
            v[4 * q + 1] = __floats2half2_rn(a.y, b.y);
            v[4 * q + 2] = __floats2half2_rn(a.z, b.z);
            v[4 * q + 3] = __floats2half2_rn(a.w, b.w);
        }
    }

    // MAE in half2 (per-thread sums only 16 values -> fp16 error ~1e-5 rel)
    float mae;
    {
        const __half2 y2 = __floats2half2_rn(__ldg(&y[rowA]), __ldg(&y[rowB]));
        __half2 acc = __habs2(__hsub2(v[0], y2));
        #pragma unroll
        for (int r = 1; r < VPT; r++)
            acc = __hadd2(acc, __habs2(__hsub2(v[r], y2)));
        const float2 f = __half22float2(acc);
        mae = f.x + f.y;
    }

    // ---- per-thread ascending bitonic sort of 16 registers ----
    intra_ct<2, 1>(v);
    intra_ct<4, 2>(v);  intra_ct<4, 1>(v);
    intra_ct<8, 4>(v);  intra_ct<8, 2>(v);  intra_ct<8, 1>(v);
    intra_desc16(v);    // k=16 final ascending merge (strides 8,4,2,1)

    // ---- normalized cross-lane merges ----
    // 16 -> 32  (rev stride 16 = lane 1; rest intra)
    rev_cross<1>(v, sub);
    intra_desc16(v);
    // 32 -> 64  (rev lane 3; asc lane 1; intra)
    rev_cross<3>(v, sub);
    asc_cross<1>(v, sub);
    intra_desc16(v);
    // 64 -> 128 (rev lane 7; asc lane 2,1; intra)
    rev_cross<7>(v, sub);
    asc_cross<2>(v, sub); asc_cross<1>(v, sub);
    intra_desc16(v);
    // 128 -> 256 (rev lane 15; asc lane 4,2,1; intra)
    rev_cross<15>(v, sub);
    asc_cross<4>(v, sub); asc_cross<2>(v, sub); asc_cross<1>(v, sub);
    intra_desc16(v);

    // ---- weighted sorted sum (rows share w_j) + mae ----
    float ws = 0.0f;
    #pragma unroll
    for (int r = 0; r < VPT; r++) {
        const float w = (float)(2 * (base + r) - (MDIM - 1));
        const float2 f = __half22float2(v[r]);
        ws = fmaf(w, f.x + f.y, ws);
    }
    float t = mae * c1 + ws * c2;

    // warp reduce (sums all 4 rows)
    #pragma unroll
    for (int off = 16; off; off >>= 1)
        t += __shfl_xor_sync(0xffffffffu, t, off);

    // per-CTA partial + last-block-done (single warp: no smem, no barriers)
    unsigned int last = 0;
    if (lane == 0) {
        g_partials[blockIdx.x] = t;
        __threadfence();
        const unsigned int old = atomicAdd(&g_count, 1u);
        last = (old == (unsigned int)(n_ctas - 1)) ? 1u : 0u;
    }
    last = __shfl_sync(0xffffffffu, last, 0);

    if (last) {
        __threadfence();
        float acc = 0.0f;
        for (int i = lane; i < n_ctas; i += 32) acc += g_partials[i];
        #pragma unroll
        for (int off = 16; off; off >>= 1)
            acc += __shfl_xor_sync(0xffffffffu, acc, off);
        if (lane == 0) {
            out[0] = acc;
            g_count = 0;   // reset for next graph replay
        }
    }
}

extern "C" void kernel_launch(void* const* d_in, const int* in_sizes, int n_in,
                              void* d_out, int out_size)
{
    const float* y_pred = (const float*)d_in[0];
    const float* y      = (const float*)d_in[1];
    float* out          = (float*)d_out;

    const int n = in_sizes[1];               // 4096 rows
    (void)n_in; (void)out_size;

    const float c1 =  1.0f / ((float)n * (float)MDIM);
    const float c2 = -1.0f / ((float)n * (float)MDIM * (float)MDIM);

    const int n_ctas = n / ROWS_PER_CTA;     // 1024
    crps_row_kernel<<<n_ctas, 32>>>(y_pred, y, c1, c2, out, n_ctas);
}

// round 17
// speedup vs baseline: 1.2132x; 1.1397x over previous
#include <cuda_runtime.h>
#include <cuda_fp16.h>

// CRPS loss: out = mean|y_pred - y| - sum_{i,k,l}|x[i,k]-x[i,l]| / (n*2*m^2)
// Sorted-row identity:  sum_{k,l}|x_k - x_l| = 2 * sum_j (2j - m + 1) x_(j)
//
// R13 config (best so far): 2 rows/warp packed half2, VPT=8, normalized
// bitonic network, 2048 warps. R17 change: break intra-round shfl
// serialization —
//  * __launch_bounds__(128, 1): allow ptxas a full register budget so the
//    8 shuffles of each cross round get 8 independent destination regs.
//  * every cross round gathers ALL partner values first, then does all
//    compare-exchanges (2-phase), exposing 8-wide ILP per round.
//  * MAE in half2 (error ~3e-6, tolerance 1e-3).
// Fused last-block-done deterministic final reduction.

#define MDIM 256
#define VPT 8
#define WARPS_PER_CTA 4
#define ROWS_PER_CTA (WARPS_PER_CTA * 2)
#define NTHREADS (WARPS_PER_CTA * 32)
#define MAX_CTAS 8192

__device__ float        g_partials[MAX_CTAS];
__device__ unsigned int g_count;   // zero-init; reset by last CTA each launch

__device__ __forceinline__ void cexa2(__half2& a, __half2& b) {
    __half2 mn = __hmin2(a, b); b = __hmax2(a, b); a = mn;
}
__device__ __forceinline__ void cexd2(__half2& a, __half2& b) {
    __half2 mx = __hmax2(a, b); b = __hmin2(a, b); a = mx;
}

// ascending intra-register descent: strides 4, 2, 1 (compile-time dirs)
__device__ __forceinline__ void intra_desc(__half2 v[VPT]) {
    cexa2(v[0], v[4]); cexa2(v[1], v[5]); cexa2(v[2], v[6]); cexa2(v[3], v[7]);
    cexa2(v[0], v[2]); cexa2(v[1], v[3]); cexa2(v[4], v[6]); cexa2(v[5], v[7]);
    cexa2(v[0], v[1]); cexa2(v[2], v[3]); cexa2(v[4], v[5]); cexa2(v[6], v[7]);
}

// reversal exchange (merge entry): partner j ^ (8*(LM+1)-1) -> lane^LM, reg 7-r
// Phase 1: gather all 8 partners into p[]. Phase 2: all compare-exchanges.
template <int LM>
__device__ __forceinline__ void rev_cross(__half2 v[VPT], int lane) {
    const bool keep_min = (lane & ((LM + 1) >> 1)) == 0;
    __half2 p[VPT];
    #pragma unroll
    for (int r = 0; r < VPT; r++)
        p[r] = __shfl_xor_sync(0xffffffffu, v[VPT - 1 - r], LM);
    #pragma unroll
    for (int r = 0; r < VPT; r++)
        v[r] = keep_min ? __hmin2(v[r], p[r]) : __hmax2(v[r], p[r]);
}

// uniform-ascending cross-lane exchange at lane stride S (2-phase for ILP)
template <int S>
__device__ __forceinline__ void asc_cross(__half2 v[VPT], int lane) {
    const bool keep_min = (lane & S) == 0;
    __half2 p[VPT];
    #pragma unroll
    for (int r = 0; r < VPT; r++)
        p[r] = __shfl_xor_sync(0xffffffffu, v[r], S);
    #pragma unroll
    for (int r = 0; r < VPT; r++)
        v[r] = keep_min ? __hmin2(v[r], p[r]) : __hmax2(v[r], p[r]);
}

__global__ void __launch_bounds__(NTHREADS, 1) crps_row_kernel(
    const float* __restrict__ y_pred,
    const float* __restrict__ y,
    float c1,   //  1/(n*m)
    float c2,   // -1/(n*m*m)
    float* __restrict__ out,
    int n_ctas)
{
    const int warp = threadIdx.x >> 5;
    const int lane = threadIdx.x & 31;
    const int rowA = (blockIdx.x * WARPS_PER_CTA + warp) * 2;
    const int rowB = rowA + 1;

    // Load 8 elements of each row; pack to half2 (x=rowA elem, y=rowB elem).
    __half2 v[VPT];
    {
        const float4* pa = (const float4*)(y_pred + rowA * MDIM + lane * VPT);
        const float4* pb = (const float4*)(y_pred + rowB * MDIM + lane * VPT);
        const float4 a0 = pa[0], a1 = pa[1];
        const float4 b0 = pb[0], b1 = pb[1];
        v[0] = __floats2half2_rn(a0.x, b0.x);
        v[1] = __floats2half2_rn(a0.y, b0.y);
        v[2] = __floats2half2_rn(a0.z, b0.z);
        v[3] = __floats2half2_rn(a0.w, b0.w);
        v[4] = __floats2half2_rn(a1.x, b1.x);
        v[5] = __floats2half2_rn(a1.y, b1.y);
        v[6] = __floats2half2_rn(a1.z, b1.z);
        v[7] = __floats2half2_rn(a1.w, b1.w);
    }

    // MAE in half2 (8 values per row per thread; fp16 error ~1e-5 rel)
    float mae;
    {
        const __half2 y2 = __floats2half2_rn(__ldg(&y[rowA]), __ldg(&y[rowB]));
        __half2 acc = __habs2(__hsub2(v[0], y2));
        #pragma unroll
        for (int r = 1; r < VPT; r++)
            acc = __hadd2(acc, __habs2(__hsub2(v[r], y2)));
        const float2 f = __half22float2(acc);
        mae = f.x + f.y;
    }

    // ---- per-thread ascending bitonic sort of the 8 registers ----
    cexa2(v[0], v[1]); cexd2(v[2], v[3]); cexa2(v[4], v[5]); cexd2(v[6], v[7]);
    cexa2(v[0], v[2]); cexa2(v[1], v[3]); cexd2(v[4], v[6]); cexd2(v[5], v[7]);
    cexa2(v[0], v[1]); cexa2(v[2], v[3]); cexd2(v[4], v[5]); cexd2(v[6], v[7]);
    cexa2(v[0], v[4]); cexa2(v[1], v[5]); cexa2(v[2], v[6]); cexa2(v[3], v[7]);
    cexa2(v[0], v[2]); cexa2(v[1], v[3]); cexa2(v[4], v[6]); cexa2(v[5], v[7]);
    cexa2(v[0], v[1]); cexa2(v[2], v[3]); cexa2(v[4], v[5]); cexa2(v[6], v[7]);

    // ---- normalized merges: reversal exchange + ascending descent ----
    // 8 -> 16
    rev_cross<1>(v, lane);
    intra_desc(v);
    // 16 -> 32
    rev_cross<3>(v, lane);
    asc_cross<1>(v, lane);
    intra_desc(v);
    // 32 -> 64
    rev_cross<7>(v, lane);
    asc_cross<2>(v, lane); asc_cross<1>(v, lane);
    intra_desc(v);
    // 64 -> 128
    rev_cross<15>(v, lane);
    asc_cross<4>(v, lane); asc_cross<2>(v, lane); asc_cross<1>(v, lane);
    intra_desc(v);
    // 128 -> 256
    rev_cross<31>(v, lane);
    asc_cross<8>(v, lane); asc_cross<4>(v, lane);
    asc_cross<2>(v, lane); asc_cross<1>(v, lane);
    intra_desc(v);

    // ---- weighted sorted sum (both rows share weight w_j) + mae ----
    float ws = 0.0f;
    #pragma unroll
    for (int r = 0; r < VPT; r++) {
        const float w = (float)(2 * (lane * VPT + r) - (MDIM - 1));
        const float2 f = __half22float2(v[r]);
        ws = fmaf(w, f.x + f.y, ws);
    }
    float t = mae * c1 + ws * c2;

    #pragma unroll
    for (int off = 16; off; off >>= 1)
        t += __shfl_xor_sync(0xffffffffu, t, off);

    __shared__ float red[WARPS_PER_CTA];
    __shared__ bool  s_last;
    if (lane == 0) red[warp] = t;
    __syncthreads();

    if (threadIdx.x == 0) {
        float s = 0.0f;
        #pragma unroll
        for (int i = 0; i < WARPS_PER_CTA; i++) s += red[i];
        g_partials[blockIdx.x] = s;
        __threadfence();
        const unsigned int old = atomicAdd(&g_count, 1u);
        s_last = (old == (unsigned int)(n_ctas - 1));
    }
    __syncthreads();

    // ---- last CTA: deterministic final reduction over per-CTA partials ----
    if (s_last) {
        __threadfence();
        float acc = 0.0f;
        for (int i = threadIdx.x; i < n_ctas; i += NTHREADS) acc += g_partials[i];
        #pragma unroll
        for (int off = 16; off; off >>= 1)
            acc += __shfl_xor_sync(0xffffffffu, acc, off);
        if (lane == 0) red[warp] = acc;
        __syncthreads();
        if (threadIdx.x == 0) {
            float s = 0.0f;
            #pragma unroll
            for (int i = 0; i < WARPS_PER_CTA; i++) s += red[i];
            out[0] = s;
            g_count = 0;   // reset for next graph replay
        }
    }
}

extern "C" void kernel_launch(void* const* d_in, const int* in_sizes, int n_in,
                              void* d_out, int out_size)
{
    const float* y_pred = (const float*)d_in[0];
    const float* y      = (const float*)d_in[1];
    float* out          = (float*)d_out;

    const int n = in_sizes[1];               // 4096 rows
    (void)n_in; (void)out_size;

    const float c1 =  1.0f / ((float)n * (float)MDIM);
    const float c2 = -1.0f / ((float)n * (float)MDIM * (float)MDIM);

    const int n_ctas = n / ROWS_PER_CTA;     // 512
    crps_row_kernel<<<n_ctas, NTHREADS>>>(y_pred, y, c1, c2, out, n_ctas);
}